// round 13
// baseline (speedup 1.0000x reference)
#include <cuda_runtime.h>
#include <cuda_fp16.h>
#include <cstdint>

#define NMAXN 500000
#define EMAX  5000000
#define BLK 256
#define SCAN_B 1024

// Scratch (__device__ globals; allocation-free rule)
__device__ uint2 g_xwh[NMAXN * 4];   // layer-1 features, fp16 x16 (32B/node)
__device__ uint2 g_xwh2[NMAXN * 4];  // layer-2 features, fp16 x16
__device__ float g_deg[NMAXN];       // dinv
__device__ int   g_cnt[NMAXN];       // in-degree (edges only)
__device__ int   g_off[NMAXN];       // CSR offsets (exclusive prefix of cnt)
__device__ int   g_cur[NMAXN];       // scatter cursors (= off, bump-allocated)
__device__ int   g_adj[EMAX];        // CSR adjacency: source node per edge, bucketed by dest
__device__ int   g_bsum[512];        // scan block sums

__device__ __forceinline__ float sigm(float v) { return 1.0f / (1.0f + __expf(-v)); }
__device__ __forceinline__ float tanh_fast(float v) {
    float a = fabsf(v);
    float e = __expf(-2.0f * a);
    return copysignf((1.0f - e) / (1.0f + e), v);
}
__device__ __forceinline__ uint2 pack4h(float a, float b, float c, float d) {
    __half2 h0 = __floats2half2_rn(a, b);
    __half2 h1 = __floats2half2_rn(c, d);
    uint2 u;
    u.x = *reinterpret_cast<unsigned*>(&h0);
    u.y = *reinterpret_cast<unsigned*>(&h1);
    return u;
}
// s[0..7] += scale * unpack8(a)
__device__ __forceinline__ void acc8(float* s, uint4 a, float scale) {
    __half2 h; float2 f;
    h = *reinterpret_cast<__half2*>(&a.x); f = __half22float2(h); s[0] = fmaf(scale, f.x, s[0]); s[1] = fmaf(scale, f.y, s[1]);
    h = *reinterpret_cast<__half2*>(&a.y); f = __half22float2(h); s[2] = fmaf(scale, f.x, s[2]); s[3] = fmaf(scale, f.y, s[3]);
    h = *reinterpret_cast<__half2*>(&a.z); f = __half22float2(h); s[4] = fmaf(scale, f.x, s[4]); s[5] = fmaf(scale, f.y, s[5]);
    h = *reinterpret_cast<__half2*>(&a.w); f = __half22float2(h); s[6] = fmaf(scale, f.x, s[6]); s[7] = fmaf(scale, f.y, s[7]);
}

// Half-gather: thread (i, p) accumulates its 8 features over the CSR bucket.
// X is indexed by [node*2 + p] (16B per half). Pair lanes share the sector.
__device__ __forceinline__ void gather8(const uint4* __restrict__ X, int i, int p,
                                        int off, int d, float s[8]) {
#pragma unroll
    for (int k = 0; k < 8; k++) s[k] = 0.f;
    int j = 0;
    for (; j + 4 <= d; j += 4) {
        int r0 = __ldg(&g_adj[off + j]);
        int r1 = __ldg(&g_adj[off + j + 1]);
        int r2 = __ldg(&g_adj[off + j + 2]);
        int r3 = __ldg(&g_adj[off + j + 3]);
        uint4 a0 = __ldg(&X[r0 * 2 + p]);
        uint4 a1 = __ldg(&X[r1 * 2 + p]);
        uint4 a2 = __ldg(&X[r2 * 2 + p]);
        uint4 a3 = __ldg(&X[r3 * 2 + p]);
        acc8(s, a0, 1.0f);
        acc8(s, a1, 1.0f);
        acc8(s, a2, 1.0f);
        acc8(s, a3, 1.0f);
    }
    for (; j < d; j++) {
        int r = __ldg(&g_adj[off + j]);
        acc8(s, __ldg(&X[r * 2 + p]), 1.0f);
    }
    acc8(s, __ldg(&X[i * 2 + p]), 2.0f);  // self loop, weight 2
}

// Exchange: own 8 values -> full 16 via pair shuffle (lanes 2k <-> 2k+1).
__device__ __forceinline__ void exch16(const float own[8], int p, float h[16]) {
#pragma unroll
    for (int k = 0; k < 8; k++) {
        float o = __shfl_xor_sync(0xffffffffu, own[k], 1);
        h[k]     = p ? o : own[k];
        h[8 + k] = p ? own[k] : o;
    }
}

// ---------------------------------------------------------------------------
// K0: zero degree counters
__global__ void k_init(int n) {
    int i = blockIdx.x * blockDim.x + threadIdx.x;
    if (i < n) g_cnt[i] = 0;
}

// K1: degree count (int)
__global__ void k_degree(const int4* __restrict__ col4, int E4) {
    int e = blockIdx.x * blockDim.x + threadIdx.x;
    if (e < E4) {
        int4 c = col4[e];
        atomicAdd(&g_cnt[c.x], 1);
        atomicAdd(&g_cnt[c.y], 1);
        atomicAdd(&g_cnt[c.z], 1);
        atomicAdd(&g_cnt[c.w], 1);
    }
}
__global__ void k_degree_tail(const int* __restrict__ col, int start, int E) {
    int e = start + blockIdx.x * blockDim.x + threadIdx.x;
    if (e < E) atomicAdd(&g_cnt[col[e]], 1);
}

// K2a: per-block exclusive scan of g_cnt -> g_off, block totals -> g_bsum
__global__ void k_scan1(int n) {
    __shared__ int wsum[32];
    int gid = blockIdx.x * SCAN_B + threadIdx.x;
    int lane = threadIdx.x & 31, wid = threadIdx.x >> 5;
    int v = (gid < n) ? g_cnt[gid] : 0;
    int x = v;
#pragma unroll
    for (int d = 1; d < 32; d <<= 1) {
        int y = __shfl_up_sync(0xffffffffu, x, d);
        if (lane >= d) x += y;
    }
    if (lane == 31) wsum[wid] = x;
    __syncthreads();
    if (wid == 0) {
        int s = wsum[lane];
#pragma unroll
        for (int d = 1; d < 32; d <<= 1) {
            int y = __shfl_up_sync(0xffffffffu, s, d);
            if (lane >= d) s += y;
        }
        wsum[lane] = s;
    }
    __syncthreads();
    int incl = x + (wid > 0 ? wsum[wid - 1] : 0);
    if (gid < n) g_off[gid] = incl - v;  // exclusive
    if (threadIdx.x == SCAN_B - 1) g_bsum[blockIdx.x] = incl;
}

// K2b: exclusive scan of block sums (nb <= 512), single block
__global__ void k_scan2(int nb) {
    __shared__ int s[512];
    int t = threadIdx.x;
    int orig = (t < nb) ? g_bsum[t] : 0;
    s[t] = orig;
    __syncthreads();
#pragma unroll
    for (int d = 1; d < 512; d <<= 1) {
        int v = (t >= d) ? s[t - d] : 0;
        __syncthreads();
        s[t] += v;
        __syncthreads();
    }
    if (t < nb) g_bsum[t] = s[t] - orig;  // exclusive
}

// K3: finish scan (off += bsum), cursor = off, dinv, xw1' fp16
__global__ void k_nodeA(const float2* __restrict__ x, const float* __restrict__ w1, int n) {
    int i = blockIdx.x * blockDim.x + threadIdx.x;
    if (i >= n) return;
    int off = g_off[i] + g_bsum[i >> 10];
    g_off[i] = off;
    g_cur[i] = off;
    float di = rsqrtf((float)g_cnt[i] + 2.0f);
    g_deg[i] = di;
    float2 xi = x[i];
    float x0 = xi.x * di, x1 = xi.y * di;
#pragma unroll
    for (int p = 0; p < 4; p++) {
        float ox = x0 * w1[4 * p + 0] + x1 * w1[16 + 4 * p + 0];
        float oy = x0 * w1[4 * p + 1] + x1 * w1[16 + 4 * p + 1];
        float oz = x0 * w1[4 * p + 2] + x1 * w1[16 + 4 * p + 2];
        float ow = x0 * w1[4 * p + 3] + x1 * w1[16 + 4 * p + 3];
        g_xwh[i * 4 + p] = pack4h(ox, oy, oz, ow);
    }
}

// K4: scatter edges into CSR buckets, 4 edges/thread (bump cursor = absolute pos)
__global__ void k_scatter4(const int4* __restrict__ row4, const int4* __restrict__ col4, int E4) {
    int e = blockIdx.x * blockDim.x + threadIdx.x;
    if (e >= E4) return;
    int4 c = col4[e];
    int4 r = row4[e];
    g_adj[atomicAdd(&g_cur[c.x], 1)] = r.x;
    g_adj[atomicAdd(&g_cur[c.y], 1)] = r.y;
    g_adj[atomicAdd(&g_cur[c.z], 1)] = r.z;
    g_adj[atomicAdd(&g_cur[c.w], 1)] = r.w;
}
__global__ void k_scatter_tail(const int* __restrict__ row, const int* __restrict__ col,
                               int start, int E) {
    int e = start + blockIdx.x * blockDim.x + threadIdx.x;
    if (e >= E) return;
    int c = __ldg(&col[e]);
    g_adj[atomicAdd(&g_cur[c], 1)] = __ldg(&row[e]);
}

// K5: gather layer 1 (2 threads/node) + GCN1 epilogue + W2 matmul -> g_xwh2
__global__ void k_gatherB(const float* __restrict__ w2, const float* __restrict__ b1, int n) {
    __shared__ float s_w[256];
    __shared__ float s_b[16];
    int tid = threadIdx.x;
    if (tid < 256) s_w[tid] = w2[tid];
    if (tid < 16) s_b[tid] = b1[tid];
    __syncthreads();
    int t = blockIdx.x * blockDim.x + tid;
    int i = t >> 1, p = t & 1;
    if (i >= n) i = n - 1;  // clamp: duplicates recompute + store identical values
    float s[8];
    gather8((const uint4*)g_xwh, i, p, g_off[i], g_cnt[i], s);
    float di = g_deg[i];
    float hown[8];
#pragma unroll
    for (int k = 0; k < 8; k++) hown[k] = fmaxf(di * s[k] + s_b[8 * p + k], 0.f);
    float h[16];
    exch16(hown, p, h);
    // own output columns: [8p, 8p+8)
    float acc[8];
#pragma unroll
    for (int k = 0; k < 8; k++) acc[k] = 0.f;
#pragma unroll
    for (int j = 0; j < 16; j++) {
        float hj = h[j];
#pragma unroll
        for (int k = 0; k < 8; k++) acc[k] = fmaf(hj, s_w[j * 16 + 8 * p + k], acc[k]);
    }
    g_xwh2[i * 4 + 2 * p]     = pack4h(di * acc[0], di * acc[1], di * acc[2], di * acc[3]);
    g_xwh2[i * 4 + 2 * p + 1] = pack4h(di * acc[4], di * acc[5], di * acc[6], di * acc[7]);
}

// Shared layout for gatherC:
//  [0:16) gcn2_b  [16:64) lin_w  [64:67) lin_b
//  [67 + l*832): WI(256) WC(256) WO(256) BI(16) BC(16) BO(16) WCO(16)
#define S_B2 0
#define S_LW 16
#define S_LB 64
#define S_L0 67
#define S_STRIDE 832

// K6: gather layer 2 (2 threads/node) + GCN2 epilogue + 3x GConvLSTM + final linear
__global__ void k_gatherC(
    const float* __restrict__ b2, const float* __restrict__ linw, const float* __restrict__ linb,
    const float* __restrict__ wi1, const float* __restrict__ wc1, const float* __restrict__ wo1,
    const float* __restrict__ bi1, const float* __restrict__ bc1, const float* __restrict__ bo1,
    const float* __restrict__ wco1,
    const float* __restrict__ wi2, const float* __restrict__ wc2, const float* __restrict__ wo2,
    const float* __restrict__ bi2, const float* __restrict__ bc2, const float* __restrict__ bo2,
    const float* __restrict__ wco2,
    const float* __restrict__ wi3, const float* __restrict__ wc3, const float* __restrict__ wo3,
    const float* __restrict__ bi3, const float* __restrict__ bc3, const float* __restrict__ bo3,
    const float* __restrict__ wco3,
    float* __restrict__ out, int n) {
    __shared__ float S[67 + 3 * S_STRIDE];
    {
        const float* srcs[24] = {b2, linw, linb,
                                 wi1, wc1, wo1, bi1, bc1, bo1, wco1,
                                 wi2, wc2, wo2, bi2, bc2, bo2, wco2,
                                 wi3, wc3, wo3, bi3, bc3, bo3, wco3};
        const int cnts[24] = {16, 48, 3,
                              256, 256, 256, 16, 16, 16, 16,
                              256, 256, 256, 16, 16, 16, 16,
                              256, 256, 256, 16, 16, 16, 16};
        int off = 0;
#pragma unroll
        for (int a = 0; a < 24; a++) {
            for (int i = threadIdx.x; i < cnts[a]; i += blockDim.x) S[off + i] = srcs[a][i];
            off += cnts[a];
        }
    }
    __syncthreads();

    int t = blockIdx.x * blockDim.x + threadIdx.x;
    int i = t >> 1, p = t & 1;
    if (i >= n) i = n - 1;  // clamp

    float s[8];
    gather8((const uint4*)g_xwh2, i, p, g_off[i], g_cnt[i], s);
    float di = g_deg[i];
    float hown[8];
#pragma unroll
    for (int k = 0; k < 8; k++) hown[k] = fmaxf(di * s[k] + S[S_B2 + 8 * p + k], 0.f);

    float h[16], t1[8], t2[8];
#pragma unroll
    for (int l = 0; l < 3; l++) {
        const float* L = &S[S_L0 + l * S_STRIDE];
        exch16(hown, p, h);
        // i-gate (own 8 cols)
#pragma unroll
        for (int k = 0; k < 8; k++) t1[k] = L[768 + 8 * p + k];
#pragma unroll
        for (int j = 0; j < 16; j++) {
            float hj = h[j];
#pragma unroll
            for (int k = 0; k < 8; k++) t1[k] = fmaf(hj, L[j * 16 + 8 * p + k], t1[k]);
        }
#pragma unroll
        for (int k = 0; k < 8; k++) t1[k] = sigm(t1[k]);
        // C = i * tanh(h@wc + bc)
#pragma unroll
        for (int k = 0; k < 8; k++) t2[k] = L[784 + 8 * p + k];
#pragma unroll
        for (int j = 0; j < 16; j++) {
            float hj = h[j];
#pragma unroll
            for (int k = 0; k < 8; k++) t2[k] = fmaf(hj, L[256 + j * 16 + 8 * p + k], t2[k]);
        }
#pragma unroll
        for (int k = 0; k < 8; k++) t2[k] = t1[k] * tanh_fast(t2[k]);
        // o-gate
#pragma unroll
        for (int k = 0; k < 8; k++) t1[k] = L[800 + 8 * p + k] + L[816 + 8 * p + k] * t2[k];
#pragma unroll
        for (int j = 0; j < 16; j++) {
            float hj = h[j];
#pragma unroll
            for (int k = 0; k < 8; k++) t1[k] = fmaf(hj, L[512 + j * 16 + 8 * p + k], t1[k]);
        }
#pragma unroll
        for (int k = 0; k < 8; k++) t1[k] = sigm(t1[k]);
        if (l < 2) {
#pragma unroll
            for (int k = 0; k < 8; k++) hown[k] = fmaxf(t1[k] * tanh_fast(t2[k]), 0.f);
        } else {
#pragma unroll
            for (int k = 0; k < 8; k++) hown[k] = fmaxf(t2[k], 0.f);  // relu(C)
        }
    }

    // out = c @ lin_w + lin_b (lin_w: [16,3]); full c via exchange, p==0 writes
    exch16(hown, p, h);
    if (p == 0) {
#pragma unroll
        for (int m = 0; m < 3; m++) {
            float acc = S[S_LB + m];
#pragma unroll
            for (int k = 0; k < 16; k++) acc = fmaf(h[k], S[S_LW + k * 3 + m], acc);
            out[i * 3 + m] = acc;
        }
    }
}

extern "C" void kernel_launch(void* const* d_in, const int* in_sizes, int n_in,
                              void* d_out, int out_size) {
    const float* x = (const float*)d_in[0];
    const int* ei = (const int*)d_in[1];
    const float* gcn1_w = (const float*)d_in[2];
    const float* gcn1_b = (const float*)d_in[3];
    const float* gcn2_w = (const float*)d_in[4];
    const float* gcn2_b = (const float*)d_in[5];
    const float* lin_w = (const float*)d_in[6];
    const float* lin_b = (const float*)d_in[7];

    int n = in_sizes[0] / 2;
    int E = in_sizes[1] / 2;
    if (n > NMAXN) n = NMAXN;
    if (E > EMAX) E = EMAX;
    const int* row = ei;
    const int* col = ei + E;

    int nblk = (n + BLK - 1) / BLK;
    int nblk2 = (2 * n + BLK - 1) / BLK;
    int nscan = (n + SCAN_B - 1) / SCAN_B;  // <= 489

    k_init<<<nblk, BLK>>>(n);

    bool vec4 = ((((unsigned long long)col) & 15ull) == 0ull) &&
                ((((unsigned long long)row) & 15ull) == 0ull);
    int E4 = vec4 ? E / 4 : 0;

    if (vec4) {
        if (E4 > 0) k_degree<<<(E4 + BLK - 1) / BLK, BLK>>>((const int4*)col, E4);
        if (E - E4 * 4 > 0) k_degree_tail<<<1, BLK>>>(col, E4 * 4, E);
    } else {
        k_degree_tail<<<(E + BLK - 1) / BLK, BLK>>>(col, 0, E);
    }

    k_scan1<<<nscan, SCAN_B>>>(n);
    k_scan2<<<1, 512>>>(nscan);
    k_nodeA<<<nblk, BLK>>>((const float2*)x, gcn1_w, n);

    if (vec4) {
        if (E4 > 0)
            k_scatter4<<<(E4 + BLK - 1) / BLK, BLK>>>((const int4*)row, (const int4*)col, E4);
        if (E - E4 * 4 > 0) k_scatter_tail<<<1, BLK>>>(row, col, E4 * 4, E);
    } else {
        k_scatter_tail<<<(E + BLK - 1) / BLK, BLK>>>(row, col, 0, E);
    }

    k_gatherB<<<nblk2, BLK>>>(gcn2_w, gcn1_b, n);
    k_gatherC<<<nblk2, BLK>>>(
        gcn2_b, lin_w, lin_b,
        (const float*)d_in[8], (const float*)d_in[9], (const float*)d_in[10],
        (const float*)d_in[11], (const float*)d_in[12], (const float*)d_in[13],
        (const float*)d_in[14],
        (const float*)d_in[15], (const float*)d_in[16], (const float*)d_in[17],
        (const float*)d_in[18], (const float*)d_in[19], (const float*)d_in[20],
        (const float*)d_in[21],
        (const float*)d_in[22], (const float*)d_in[23], (const float*)d_in[24],
        (const float*)d_in[25], (const float*)d_in[26], (const float*)d_in[27],
        (const float*)d_in[28],
        (float*)d_out, n);
}

// round 14
// speedup vs baseline: 1.0085x; 1.0085x over previous
#include <cuda_runtime.h>
#include <cuda_fp16.h>
#include <cstdint>

#define NMAXN 500000
#define MAXDEG 64
#define BLK 256

// Scratch (__device__ globals; allocation-free rule)
__device__ uint2 g_xwh[NMAXN * 4];        // layer-1 features, fp16 x16 (32B/node)
__device__ uint2 g_xwh2[NMAXN * 4];       // layer-2 features, fp16 x16
__device__ float g_deg[NMAXN];            // dinv
__device__ int   g_cnt[NMAXN];            // in-degree, built by scatter
__device__ int   g_adj[NMAXN * MAXDEG];   // fixed-stride adjacency buckets

__device__ __forceinline__ float sigm(float v) { return 1.0f / (1.0f + __expf(-v)); }
__device__ __forceinline__ float tanh_fast(float v) {
    float a = fabsf(v);
    float e = __expf(-2.0f * a);
    return copysignf((1.0f - e) / (1.0f + e), v);
}
__device__ __forceinline__ uint2 pack4h(float a, float b, float c, float d) {
    __half2 h0 = __floats2half2_rn(a, b);
    __half2 h1 = __floats2half2_rn(c, d);
    uint2 u;
    u.x = *reinterpret_cast<unsigned*>(&h0);
    u.y = *reinterpret_cast<unsigned*>(&h1);
    return u;
}
// s[0..7] += scale * unpack8(a)
__device__ __forceinline__ void acc8(float* s, uint4 a, float scale) {
    __half2 h; float2 f;
    h = *reinterpret_cast<__half2*>(&a.x); f = __half22float2(h); s[0] = fmaf(scale, f.x, s[0]); s[1] = fmaf(scale, f.y, s[1]);
    h = *reinterpret_cast<__half2*>(&a.y); f = __half22float2(h); s[2] = fmaf(scale, f.x, s[2]); s[3] = fmaf(scale, f.y, s[3]);
    h = *reinterpret_cast<__half2*>(&a.z); f = __half22float2(h); s[4] = fmaf(scale, f.x, s[4]); s[5] = fmaf(scale, f.y, s[5]);
    h = *reinterpret_cast<__half2*>(&a.w); f = __half22float2(h); s[6] = fmaf(scale, f.x, s[6]); s[7] = fmaf(scale, f.y, s[7]);
}

// Half-gather: thread (i, p) accumulates its 8 features over bucket [i*MAXDEG, +d).
// X indexed by [node*2 + p] (16B per half); pair lanes share the node's 32B sector.
__device__ __forceinline__ void gather8(const uint4* __restrict__ X, int i, int p,
                                        int d, float s[8]) {
#pragma unroll
    for (int k = 0; k < 8; k++) s[k] = 0.f;
    int off = i * MAXDEG;
    int j = 0;
    for (; j + 4 <= d; j += 4) {
        int r0 = __ldg(&g_adj[off + j]);
        int r1 = __ldg(&g_adj[off + j + 1]);
        int r2 = __ldg(&g_adj[off + j + 2]);
        int r3 = __ldg(&g_adj[off + j + 3]);
        uint4 a0 = __ldg(&X[r0 * 2 + p]);
        uint4 a1 = __ldg(&X[r1 * 2 + p]);
        uint4 a2 = __ldg(&X[r2 * 2 + p]);
        uint4 a3 = __ldg(&X[r3 * 2 + p]);
        acc8(s, a0, 1.0f);
        acc8(s, a1, 1.0f);
        acc8(s, a2, 1.0f);
        acc8(s, a3, 1.0f);
    }
    for (; j < d; j++) {
        int r = __ldg(&g_adj[off + j]);
        acc8(s, __ldg(&X[r * 2 + p]), 1.0f);
    }
    acc8(s, __ldg(&X[i * 2 + p]), 2.0f);  // self loop, weight 2
}

// Exchange: own 8 values -> full 16 via pair shuffle (lanes 2k <-> 2k+1).
__device__ __forceinline__ void exch16(const float own[8], int p, float h[16]) {
#pragma unroll
    for (int k = 0; k < 8; k++) {
        float o = __shfl_xor_sync(0xffffffffu, own[k], 1);
        h[k]     = p ? o : own[k];
        h[8 + k] = p ? own[k] : o;
    }
}

// ---------------------------------------------------------------------------
// K0: zero degree counters
__global__ void k_init(int n) {
    int i = blockIdx.x * blockDim.x + threadIdx.x;
    if (i < n) g_cnt[i] = 0;
}

// K1: scatter edges into fixed-stride buckets; the bump atomic IS the degree count
__global__ void k_scatter(const int* __restrict__ row, const int* __restrict__ col, int E) {
    int e = blockIdx.x * blockDim.x + threadIdx.x;
    if (e >= E) return;
    int c = __ldg(&col[e]);
    int slot = atomicAdd(&g_cnt[c], 1);
    if (slot < MAXDEG) g_adj[c * MAXDEG + slot] = __ldg(&row[e]);
}

// K2: dinv = rsqrt(cnt+2); xw1' = (x @ W1) * dinv, fp16
__global__ void k_nodeA(const float2* __restrict__ x, const float* __restrict__ w1, int n) {
    int i = blockIdx.x * blockDim.x + threadIdx.x;
    if (i >= n) return;
    float di = rsqrtf((float)g_cnt[i] + 2.0f);
    g_deg[i] = di;
    float2 xi = x[i];
    float x0 = xi.x * di, x1 = xi.y * di;
#pragma unroll
    for (int p = 0; p < 4; p++) {
        float ox = x0 * w1[4 * p + 0] + x1 * w1[16 + 4 * p + 0];
        float oy = x0 * w1[4 * p + 1] + x1 * w1[16 + 4 * p + 1];
        float oz = x0 * w1[4 * p + 2] + x1 * w1[16 + 4 * p + 2];
        float ow = x0 * w1[4 * p + 3] + x1 * w1[16 + 4 * p + 3];
        g_xwh[i * 4 + p] = pack4h(ox, oy, oz, ow);
    }
}

// K3: gather layer 1 (2 threads/node) + GCN1 epilogue + W2 matmul -> g_xwh2
__global__ void k_gatherB(const float* __restrict__ w2, const float* __restrict__ b1, int n) {
    __shared__ float s_w[256];
    __shared__ float s_b[16];
    int tid = threadIdx.x;
    if (tid < 256) s_w[tid] = w2[tid];
    if (tid < 16) s_b[tid] = b1[tid];
    __syncthreads();
    int t = blockIdx.x * blockDim.x + tid;
    int i = t >> 1, p = t & 1;
    if (i >= n) i = n - 1;  // clamp: duplicates recompute + store identical values
    int d = g_cnt[i];
    if (d > MAXDEG) d = MAXDEG;
    float s[8];
    gather8((const uint4*)g_xwh, i, p, d, s);
    float di = g_deg[i];
    float hown[8];
#pragma unroll
    for (int k = 0; k < 8; k++) hown[k] = fmaxf(di * s[k] + s_b[8 * p + k], 0.f);
    float h[16];
    exch16(hown, p, h);
    // own output columns: [8p, 8p+8)
    float acc[8];
#pragma unroll
    for (int k = 0; k < 8; k++) acc[k] = 0.f;
#pragma unroll
    for (int j = 0; j < 16; j++) {
        float hj = h[j];
#pragma unroll
        for (int k = 0; k < 8; k++) acc[k] = fmaf(hj, s_w[j * 16 + 8 * p + k], acc[k]);
    }
    g_xwh2[i * 4 + 2 * p]     = pack4h(di * acc[0], di * acc[1], di * acc[2], di * acc[3]);
    g_xwh2[i * 4 + 2 * p + 1] = pack4h(di * acc[4], di * acc[5], di * acc[6], di * acc[7]);
}

// Shared layout for gatherC:
//  [0:16) gcn2_b  [16:64) lin_w  [64:67) lin_b
//  [67 + l*832): WI(256) WC(256) WO(256) BI(16) BC(16) BO(16) WCO(16)
#define S_B2 0
#define S_LW 16
#define S_LB 64
#define S_L0 67
#define S_STRIDE 832

// K4: gather layer 2 (2 threads/node) + GCN2 epilogue + 3x GConvLSTM + final linear
__global__ void k_gatherC(
    const float* __restrict__ b2, const float* __restrict__ linw, const float* __restrict__ linb,
    const float* __restrict__ wi1, const float* __restrict__ wc1, const float* __restrict__ wo1,
    const float* __restrict__ bi1, const float* __restrict__ bc1, const float* __restrict__ bo1,
    const float* __restrict__ wco1,
    const float* __restrict__ wi2, const float* __restrict__ wc2, const float* __restrict__ wo2,
    const float* __restrict__ bi2, const float* __restrict__ bc2, const float* __restrict__ bo2,
    const float* __restrict__ wco2,
    const float* __restrict__ wi3, const float* __restrict__ wc3, const float* __restrict__ wo3,
    const float* __restrict__ bi3, const float* __restrict__ bc3, const float* __restrict__ bo3,
    const float* __restrict__ wco3,
    float* __restrict__ out, int n) {
    __shared__ float S[67 + 3 * S_STRIDE];
    {
        const float* srcs[24] = {b2, linw, linb,
                                 wi1, wc1, wo1, bi1, bc1, bo1, wco1,
                                 wi2, wc2, wo2, bi2, bc2, bo2, wco2,
                                 wi3, wc3, wo3, bi3, bc3, bo3, wco3};
        const int cnts[24] = {16, 48, 3,
                              256, 256, 256, 16, 16, 16, 16,
                              256, 256, 256, 16, 16, 16, 16,
                              256, 256, 256, 16, 16, 16, 16};
        int off = 0;
#pragma unroll
        for (int a = 0; a < 24; a++) {
            for (int i = threadIdx.x; i < cnts[a]; i += blockDim.x) S[off + i] = srcs[a][i];
            off += cnts[a];
        }
    }
    __syncthreads();

    int t = blockIdx.x * blockDim.x + threadIdx.x;
    int i = t >> 1, p = t & 1;
    if (i >= n) i = n - 1;  // clamp

    int d = g_cnt[i];
    if (d > MAXDEG) d = MAXDEG;
    float s[8];
    gather8((const uint4*)g_xwh2, i, p, d, s);
    float di = g_deg[i];
    float hown[8];
#pragma unroll
    for (int k = 0; k < 8; k++) hown[k] = fmaxf(di * s[k] + S[S_B2 + 8 * p + k], 0.f);

    float h[16], t1[8], t2[8];
#pragma unroll
    for (int l = 0; l < 3; l++) {
        const float* L = &S[S_L0 + l * S_STRIDE];
        exch16(hown, p, h);
        // i-gate (own 8 cols)
#pragma unroll
        for (int k = 0; k < 8; k++) t1[k] = L[768 + 8 * p + k];
#pragma unroll
        for (int j = 0; j < 16; j++) {
            float hj = h[j];
#pragma unroll
            for (int k = 0; k < 8; k++) t1[k] = fmaf(hj, L[j * 16 + 8 * p + k], t1[k]);
        }
#pragma unroll
        for (int k = 0; k < 8; k++) t1[k] = sigm(t1[k]);
        // C = i * tanh(h@wc + bc)
#pragma unroll
        for (int k = 0; k < 8; k++) t2[k] = L[784 + 8 * p + k];
#pragma unroll
        for (int j = 0; j < 16; j++) {
            float hj = h[j];
#pragma unroll
            for (int k = 0; k < 8; k++) t2[k] = fmaf(hj, L[256 + j * 16 + 8 * p + k], t2[k]);
        }
#pragma unroll
        for (int k = 0; k < 8; k++) t2[k] = t1[k] * tanh_fast(t2[k]);
        // o-gate
#pragma unroll
        for (int k = 0; k < 8; k++) t1[k] = L[800 + 8 * p + k] + L[816 + 8 * p + k] * t2[k];
#pragma unroll
        for (int j = 0; j < 16; j++) {
            float hj = h[j];
#pragma unroll
            for (int k = 0; k < 8; k++) t1[k] = fmaf(hj, L[512 + j * 16 + 8 * p + k], t1[k]);
        }
#pragma unroll
        for (int k = 0; k < 8; k++) t1[k] = sigm(t1[k]);
        if (l < 2) {
#pragma unroll
            for (int k = 0; k < 8; k++) hown[k] = fmaxf(t1[k] * tanh_fast(t2[k]), 0.f);
        } else {
#pragma unroll
            for (int k = 0; k < 8; k++) hown[k] = fmaxf(t2[k], 0.f);  // relu(C)
        }
    }

    // out = c @ lin_w + lin_b (lin_w: [16,3]); full c via exchange, p==0 writes
    exch16(hown, p, h);
    if (p == 0) {
#pragma unroll
        for (int m = 0; m < 3; m++) {
            float acc = S[S_LB + m];
#pragma unroll
            for (int k = 0; k < 16; k++) acc = fmaf(h[k], S[S_LW + k * 3 + m], acc);
            out[i * 3 + m] = acc;
        }
    }
}

extern "C" void kernel_launch(void* const* d_in, const int* in_sizes, int n_in,
                              void* d_out, int out_size) {
    const float* x = (const float*)d_in[0];
    const int* ei = (const int*)d_in[1];
    const float* gcn1_w = (const float*)d_in[2];
    const float* gcn1_b = (const float*)d_in[3];
    const float* gcn2_w = (const float*)d_in[4];
    const float* gcn2_b = (const float*)d_in[5];
    const float* lin_w = (const float*)d_in[6];
    const float* lin_b = (const float*)d_in[7];

    int n = in_sizes[0] / 2;
    int E = in_sizes[1] / 2;
    if (n > NMAXN) n = NMAXN;
    const int* row = ei;
    const int* col = ei + E;

    int nblk = (n + BLK - 1) / BLK;
    int nblk2 = (2 * n + BLK - 1) / BLK;

    k_init<<<nblk, BLK>>>(n);
    k_scatter<<<(E + BLK - 1) / BLK, BLK>>>(row, col, E);
    k_nodeA<<<nblk, BLK>>>((const float2*)x, gcn1_w, n);
    k_gatherB<<<nblk2, BLK>>>(gcn2_w, gcn1_b, n);
    k_gatherC<<<nblk2, BLK>>>(
        gcn2_b, lin_w, lin_b,
        (const float*)d_in[8], (const float*)d_in[9], (const float*)d_in[10],
        (const float*)d_in[11], (const float*)d_in[12], (const float*)d_in[13],
        (const float*)d_in[14],
        (const float*)d_in[15], (const float*)d_in[16], (const float*)d_in[17],
        (const float*)d_in[18], (const float*)d_in[19], (const float*)d_in[20],
        (const float*)d_in[21],
        (const float*)d_in[22], (const float*)d_in[23], (const float*)d_in[24],
        (const float*)d_in[25], (const float*)d_in[26], (const float*)d_in[27],
        (const float*)d_in[28],
        (float*)d_out, n);
}

// round 16
// speedup vs baseline: 1.0135x; 1.0050x over previous
#include <cuda_runtime.h>
#include <cuda_fp16.h>
#include <cstdint>

#define NMAXN 500000
#define MAXDEG 32
#define OVF_CAP 4096
#define BLK 256

// Scratch (__device__ globals; allocation-free rule)
__device__ uint2 g_xwh[NMAXN * 4];        // layer-1 features, fp16 x16 (32B/node)
__device__ uint2 g_xwh2[NMAXN * 4];       // layer-2 features, fp16 x16
__device__ float g_deg[NMAXN];            // dinv
__device__ int   g_cnt[NMAXN];            // in-degree, built by scatter
__device__ int   g_adj[NMAXN * MAXDEG];   // fixed-stride adjacency buckets (64MB, L2-resident)
__device__ int   g_ovf_cnt;               // overflow entries
__device__ int   g_ovf_dst[OVF_CAP];
__device__ int   g_ovf_src[OVF_CAP];

__device__ __forceinline__ float sigm(float v) { return 1.0f / (1.0f + __expf(-v)); }
__device__ __forceinline__ float tanh_fast(float v) {
    float a = fabsf(v);
    float e = __expf(-2.0f * a);
    return copysignf((1.0f - e) / (1.0f + e), v);
}
__device__ __forceinline__ uint2 pack4h(float a, float b, float c, float d) {
    __half2 h0 = __floats2half2_rn(a, b);
    __half2 h1 = __floats2half2_rn(c, d);
    uint2 u;
    u.x = *reinterpret_cast<unsigned*>(&h0);
    u.y = *reinterpret_cast<unsigned*>(&h1);
    return u;
}
// s[0..7] += scale * unpack8(a)
__device__ __forceinline__ void acc8(float* s, uint4 a, float scale) {
    __half2 h; float2 f;
    h = *reinterpret_cast<__half2*>(&a.x); f = __half22float2(h); s[0] = fmaf(scale, f.x, s[0]); s[1] = fmaf(scale, f.y, s[1]);
    h = *reinterpret_cast<__half2*>(&a.y); f = __half22float2(h); s[2] = fmaf(scale, f.x, s[2]); s[3] = fmaf(scale, f.y, s[3]);
    h = *reinterpret_cast<__half2*>(&a.z); f = __half22float2(h); s[4] = fmaf(scale, f.x, s[4]); s[5] = fmaf(scale, f.y, s[5]);
    h = *reinterpret_cast<__half2*>(&a.w); f = __half22float2(h); s[6] = fmaf(scale, f.x, s[6]); s[7] = fmaf(scale, f.y, s[7]);
}

// Half-gather: thread (i, p) accumulates its 8 features over bucket [i*MAXDEG, +d),
// then the (normally empty) overflow list, then self-loop (weight 2).
__device__ __forceinline__ void gather8(const uint4* __restrict__ X, int i, int p,
                                        int d, float s[8]) {
#pragma unroll
    for (int k = 0; k < 8; k++) s[k] = 0.f;
    int off = i * MAXDEG;
    int j = 0;
    for (; j + 4 <= d; j += 4) {
        int r0 = __ldg(&g_adj[off + j]);
        int r1 = __ldg(&g_adj[off + j + 1]);
        int r2 = __ldg(&g_adj[off + j + 2]);
        int r3 = __ldg(&g_adj[off + j + 3]);
        uint4 a0 = __ldg(&X[r0 * 2 + p]);
        uint4 a1 = __ldg(&X[r1 * 2 + p]);
        uint4 a2 = __ldg(&X[r2 * 2 + p]);
        uint4 a3 = __ldg(&X[r3 * 2 + p]);
        acc8(s, a0, 1.0f);
        acc8(s, a1, 1.0f);
        acc8(s, a2, 1.0f);
        acc8(s, a3, 1.0f);
    }
    for (; j < d; j++) {
        int r = __ldg(&g_adj[off + j]);
        acc8(s, __ldg(&X[r * 2 + p]), 1.0f);
    }
    // overflow entries (expected 0; broadcast reads, same for all threads)
    int novf = g_ovf_cnt;
    if (novf > OVF_CAP) novf = OVF_CAP;
    for (int k = 0; k < novf; k++) {
        if (g_ovf_dst[k] == i) acc8(s, __ldg(&X[g_ovf_src[k] * 2 + p]), 1.0f);
    }
    acc8(s, __ldg(&X[i * 2 + p]), 2.0f);  // self loop, weight 2
}

// Exchange: own 8 values -> full 16 via pair shuffle (lanes 2k <-> 2k+1).
__device__ __forceinline__ void exch16(const float own[8], int p, float h[16]) {
#pragma unroll
    for (int k = 0; k < 8; k++) {
        float o = __shfl_xor_sync(0xffffffffu, own[k], 1);
        h[k]     = p ? o : own[k];
        h[8 + k] = p ? own[k] : o;
    }
}

// ---------------------------------------------------------------------------
// K0: zero degree counters + overflow counter
__global__ void k_init(int n) {
    int i = blockIdx.x * blockDim.x + threadIdx.x;
    if (i < n) g_cnt[i] = 0;
    if (i == 0) g_ovf_cnt = 0;
}

// K1: scatter edges into fixed-stride buckets; bump atomic IS the degree count.
// Rare overflow (slot >= MAXDEG) goes to the compact overflow list.
__global__ void k_scatter(const int* __restrict__ row, const int* __restrict__ col, int E) {
    int e = blockIdx.x * blockDim.x + threadIdx.x;
    if (e >= E) return;
    int c = __ldg(&col[e]);
    int r = __ldg(&row[e]);
    int slot = atomicAdd(&g_cnt[c], 1);
    if (slot < MAXDEG) {
        g_adj[c * MAXDEG + slot] = r;
    } else {
        int o = atomicAdd(&g_ovf_cnt, 1);
        if (o < OVF_CAP) { g_ovf_dst[o] = c; g_ovf_src[o] = r; }
    }
}

// K2: dinv = rsqrt(cnt+2); xw1' = (x @ W1) * dinv, fp16
__global__ void k_nodeA(const float2* __restrict__ x, const float* __restrict__ w1, int n) {
    int i = blockIdx.x * blockDim.x + threadIdx.x;
    if (i >= n) return;
    float di = rsqrtf((float)g_cnt[i] + 2.0f);
    g_deg[i] = di;
    float2 xi = x[i];
    float x0 = xi.x * di, x1 = xi.y * di;
#pragma unroll
    for (int p = 0; p < 4; p++) {
        float ox = x0 * w1[4 * p + 0] + x1 * w1[16 + 4 * p + 0];
        float oy = x0 * w1[4 * p + 1] + x1 * w1[16 + 4 * p + 1];
        float oz = x0 * w1[4 * p + 2] + x1 * w1[16 + 4 * p + 2];
        float ow = x0 * w1[4 * p + 3] + x1 * w1[16 + 4 * p + 3];
        g_xwh[i * 4 + p] = pack4h(ox, oy, oz, ow);
    }
}

// K3: gather layer 1 (2 threads/node) + GCN1 epilogue + W2 matmul -> g_xwh2
__global__ void k_gatherB(const float* __restrict__ w2, const float* __restrict__ b1, int n) {
    __shared__ float s_w[256];
    __shared__ float s_b[16];
    int tid = threadIdx.x;
    if (tid < 256) s_w[tid] = w2[tid];
    if (tid < 16) s_b[tid] = b1[tid];
    __syncthreads();
    int t = blockIdx.x * blockDim.x + tid;
    int i = t >> 1, p = t & 1;
    if (i >= n) i = n - 1;  // clamp: duplicates recompute + store identical values
    int d = g_cnt[i];
    if (d > MAXDEG) d = MAXDEG;
    float s[8];
    gather8((const uint4*)g_xwh, i, p, d, s);
    float di = g_deg[i];
    float hown[8];
#pragma unroll
    for (int k = 0; k < 8; k++) hown[k] = fmaxf(di * s[k] + s_b[8 * p + k], 0.f);
    float h[16];
    exch16(hown, p, h);
    // own output columns: [8p, 8p+8)
    float acc[8];
#pragma unroll
    for (int k = 0; k < 8; k++) acc[k] = 0.f;
#pragma unroll
    for (int j = 0; j < 16; j++) {
        float hj = h[j];
#pragma unroll
        for (int k = 0; k < 8; k++) acc[k] = fmaf(hj, s_w[j * 16 + 8 * p + k], acc[k]);
    }
    g_xwh2[i * 4 + 2 * p]     = pack4h(di * acc[0], di * acc[1], di * acc[2], di * acc[3]);
    g_xwh2[i * 4 + 2 * p + 1] = pack4h(di * acc[4], di * acc[5], di * acc[6], di * acc[7]);
}

// Shared layout for gatherC:
//  [0:16) gcn2_b  [16:64) lin_w  [64:67) lin_b
//  [67 + l*832): WI(256) WC(256) WO(256) BI(16) BC(16) BO(16) WCO(16)
#define S_B2 0
#define S_LW 16
#define S_LB 64
#define S_L0 67
#define S_STRIDE 832

// K4: gather layer 2 (2 threads/node) + GCN2 epilogue + 3x GConvLSTM + final linear
__global__ void k_gatherC(
    const float* __restrict__ b2, const float* __restrict__ linw, const float* __restrict__ linb,
    const float* __restrict__ wi1, const float* __restrict__ wc1, const float* __restrict__ wo1,
    const float* __restrict__ bi1, const float* __restrict__ bc1, const float* __restrict__ bo1,
    const float* __restrict__ wco1,
    const float* __restrict__ wi2, const float* __restrict__ wc2, const float* __restrict__ wo2,
    const float* __restrict__ bi2, const float* __restrict__ bc2, const float* __restrict__ bo2,
    const float* __restrict__ wco2,
    const float* __restrict__ wi3, const float* __restrict__ wc3, const float* __restrict__ wo3,
    const float* __restrict__ bi3, const float* __restrict__ bc3, const float* __restrict__ bo3,
    const float* __restrict__ wco3,
    float* __restrict__ out, int n) {
    __shared__ float S[67 + 3 * S_STRIDE];
    {
        const float* srcs[24] = {b2, linw, linb,
                                 wi1, wc1, wo1, bi1, bc1, bo1, wco1,
                                 wi2, wc2, wo2, bi2, bc2, bo2, wco2,
                                 wi3, wc3, wo3, bi3, bc3, bo3, wco3};
        const int cnts[24] = {16, 48, 3,
                              256, 256, 256, 16, 16, 16, 16,
                              256, 256, 256, 16, 16, 16, 16,
                              256, 256, 256, 16, 16, 16, 16};
        int off = 0;
#pragma unroll
        for (int a = 0; a < 24; a++) {
            for (int i = threadIdx.x; i < cnts[a]; i += blockDim.x) S[off + i] = srcs[a][i];
            off += cnts[a];
        }
    }
    __syncthreads();

    int t = blockIdx.x * blockDim.x + threadIdx.x;
    int i = t >> 1, p = t & 1;
    if (i >= n) i = n - 1;  // clamp

    int d = g_cnt[i];
    if (d > MAXDEG) d = MAXDEG;
    float s[8];
    gather8((const uint4*)g_xwh2, i, p, d, s);
    float di = g_deg[i];
    float hown[8];
#pragma unroll
    for (int k = 0; k < 8; k++) hown[k] = fmaxf(di * s[k] + S[S_B2 + 8 * p + k], 0.f);

    float h[16], t1[8], t2[8];
#pragma unroll
    for (int l = 0; l < 3; l++) {
        const float* L = &S[S_L0 + l * S_STRIDE];
        exch16(hown, p, h);
        // i-gate (own 8 cols)
#pragma unroll
        for (int k = 0; k < 8; k++) t1[k] = L[768 + 8 * p + k];
#pragma unroll
        for (int j = 0; j < 16; j++) {
            float hj = h[j];
#pragma unroll
            for (int k = 0; k < 8; k++) t1[k] = fmaf(hj, L[j * 16 + 8 * p + k], t1[k]);
        }
#pragma unroll
        for (int k = 0; k < 8; k++) t1[k] = sigm(t1[k]);
        // C = i * tanh(h@wc + bc)
#pragma unroll
        for (int k = 0; k < 8; k++) t2[k] = L[784 + 8 * p + k];
#pragma unroll
        for (int j = 0; j < 16; j++) {
            float hj = h[j];
#pragma unroll
            for (int k = 0; k < 8; k++) t2[k] = fmaf(hj, L[256 + j * 16 + 8 * p + k], t2[k]);
        }
#pragma unroll
        for (int k = 0; k < 8; k++) t2[k] = t1[k] * tanh_fast(t2[k]);
        // o-gate
#pragma unroll
        for (int k = 0; k < 8; k++) t1[k] = L[800 + 8 * p + k] + L[816 + 8 * p + k] * t2[k];
#pragma unroll
        for (int j = 0; j < 16; j++) {
            float hj = h[j];
#pragma unroll
            for (int k = 0; k < 8; k++) t1[k] = fmaf(hj, L[512 + j * 16 + 8 * p + k], t1[k]);
        }
#pragma unroll
        for (int k = 0; k < 8; k++) t1[k] = sigm(t1[k]);
        if (l < 2) {
#pragma unroll
            for (int k = 0; k < 8; k++) hown[k] = fmaxf(t1[k] * tanh_fast(t2[k]), 0.f);
        } else {
#pragma unroll
            for (int k = 0; k < 8; k++) hown[k] = fmaxf(t2[k], 0.f);  // relu(C)
        }
    }

    // out = c @ lin_w + lin_b (lin_w: [16,3]); full c via exchange, p==0 writes
    exch16(hown, p, h);
    if (p == 0) {
#pragma unroll
        for (int m = 0; m < 3; m++) {
            float acc = S[S_LB + m];
#pragma unroll
            for (int k = 0; k < 16; k++) acc = fmaf(h[k], S[S_LW + k * 3 + m], acc);
            out[i * 3 + m] = acc;
        }
    }
}

extern "C" void kernel_launch(void* const* d_in, const int* in_sizes, int n_in,
                              void* d_out, int out_size) {
    const float* x = (const float*)d_in[0];
    const int* ei = (const int*)d_in[1];
    const float* gcn1_w = (const float*)d_in[2];
    const float* gcn1_b = (const float*)d_in[3];
    const float* gcn2_w = (const float*)d_in[4];
    const float* gcn2_b = (const float*)d_in[5];
    const float* lin_w = (const float*)d_in[6];
    const float* lin_b = (const float*)d_in[7];

    int n = in_sizes[0] / 2;
    int E = in_sizes[1] / 2;
    if (n > NMAXN) n = NMAXN;
    const int* row = ei;
    const int* col = ei + E;

    int nblk = (n + BLK - 1) / BLK;
    int nblk2 = (2 * n + BLK - 1) / BLK;

    k_init<<<nblk, BLK>>>(n);
    k_scatter<<<(E + BLK - 1) / BLK, BLK>>>(row, col, E);
    k_nodeA<<<nblk, BLK>>>((const float2*)x, gcn1_w, n);
    k_gatherB<<<nblk2, BLK>>>(gcn2_w, gcn1_b, n);
    k_gatherC<<<nblk2, BLK>>>(
        gcn2_b, lin_w, lin_b,
        (const float*)d_in[8], (const float*)d_in[9], (const float*)d_in[10],
        (const float*)d_in[11], (const float*)d_in[12], (const float*)d_in[13],
        (const float*)d_in[14],
        (const float*)d_in[15], (const float*)d_in[16], (const float*)d_in[17],
        (const float*)d_in[18], (const float*)d_in[19], (const float*)d_in[20],
        (const float*)d_in[21],
        (const float*)d_in[22], (const float*)d_in[23], (const float*)d_in[24],
        (const float*)d_in[25], (const float*)d_in[26], (const float*)d_in[27],
        (const float*)d_in[28],
        (float*)d_out, n);
}